// round 1
// baseline (speedup 1.0000x reference)
#include <cuda_runtime.h>
#include <math.h>

#define B 8
#define C 128
#define H 128
#define W 128
#define L 41
#define HW (H*W)

// ---- scratch (static device globals; no allocations) ----
__device__ float g_fuse[(size_t)B*C*H*W];   // 64 MB conv output
__device__ float g_sums[2*B*L*C];           // per-class channel sums (set0=d, set1=fuse)
__device__ int   g_cnt[B*L];                // label histogram
__device__ float g_gates[2*B*C];            // final sigmoid gates

// ============================================================================
// Conv3x3 over virtual 256-ch input: ch<128 -> r+d ; ch>=128 -> r*sigmoid(d)
// Block: (b, h, co-block of 64) ; 256 threads ; thread tile 8co x 4px.
// ============================================================================
__global__ void __launch_bounds__(256) conv_kernel(const float* __restrict__ r,
                                                   const float* __restrict__ d,
                                                   const float* __restrict__ cw)
{
    __shared__ float si[8][3][132];   // [ci_chunk][row][x] x=col+1, cols -1..128
    __shared__ float sw[72][64];      // [ci*9+tap][co_rel]

    const int t   = threadIdx.x;
    const int h   = blockIdx.x;
    const int cb  = blockIdx.y;      // 0/1 -> co base 0/64
    const int b   = blockIdx.z;
    const int cog = t & 7;           // 8 co-groups (8 co each)
    const int pxg = t >> 3;          // 32 pixel groups (4 px each)
    const int px0 = pxg * 4;

    const int co_rel_w = t >> 2;     // weight staging: thread -> (co_rel, quarter)
    const int qw       = t & 3;

    float acc[8][4];
    #pragma unroll
    for (int i = 0; i < 8; i++)
        #pragma unroll
        for (int p = 0; p < 4; p++) acc[i][p] = 0.f;

    for (int cic = 0; cic < 256; cic += 8) {
        // ---- stage weights: 64co x 8ci x 9 taps (72 contiguous floats per co) ----
        {
            const float* wg = cw + (size_t)(cb*64 + co_rel_w)*2304 + cic*9 + qw*18;
            #pragma unroll
            for (int s = 0; s < 18; s++) sw[qw*18 + s][co_rel_w] = wg[s];
        }
        // ---- stage input: 8ci x 3 rows x 130 cols (zero-padded halo) ----
        for (int i = t; i < 8*3*132; i += 256) {
            int cc  = i / 396;
            int rem = i - cc*396;
            int ry  = rem / 132;
            int xx  = rem - ry*132;
            int col = xx - 1;
            int row = h - 1 + ry;
            float v = 0.f;
            if ((unsigned)col < 128u && (unsigned)row < 128u) {
                int civ = cic + cc;
                int ch  = civ & 127;
                int off = ((b*128 + ch)*128 + row)*128 + col;
                float rv = r[off], dv = d[off];
                v = (civ < 128) ? (rv + dv) : (rv * (1.f / (1.f + expf(-dv))));
            }
            si[cc][ry][xx] = v;
        }
        __syncthreads();

        #pragma unroll
        for (int cc = 0; cc < 8; cc++) {
            #pragma unroll
            for (int ky = 0; ky < 3; ky++) {
                float in6[6];
                #pragma unroll
                for (int u = 0; u < 6; u++) in6[u] = si[cc][ky][px0 + u];
                #pragma unroll
                for (int kx = 0; kx < 3; kx++) {
                    const float4* wp = (const float4*)&sw[cc*9 + ky*3 + kx][cog*8];
                    float4 wa = wp[0], wb = wp[1];
                    float wv[8] = {wa.x, wa.y, wa.z, wa.w, wb.x, wb.y, wb.z, wb.w};
                    #pragma unroll
                    for (int i = 0; i < 8; i++)
                        #pragma unroll
                        for (int p = 0; p < 4; p++)
                            acc[i][p] += wv[i] * in6[p + kx];
                }
            }
        }
        __syncthreads();
    }

    #pragma unroll
    for (int i = 0; i < 8; i++) {
        int co = cb*64 + cog*8 + i;
        float4 o4 = make_float4(acc[i][0], acc[i][1], acc[i][2], acc[i][3]);
        *(float4*)&g_fuse[(((size_t)b*128 + co)*128 + h)*128 + px0] = o4;
    }
}

// ============================================================================
// Zero the segment-sum scratch (runs every replay)
// ============================================================================
__global__ void zero_kernel()
{
    int i = blockIdx.x * blockDim.x + threadIdx.x;
    if (i < 2*B*L*C) g_sums[i] = 0.f;
}

// ============================================================================
// Label histogram per batch (nearest-resize: label[b, 4y, 4x])
// ============================================================================
__global__ void __launch_bounds__(256) hist_kernel(const int* __restrict__ label)
{
    __shared__ int hc[L];
    int t = threadIdx.x, b = blockIdx.x;
    if (t < L) hc[t] = 0;
    __syncthreads();
    for (int p = t; p < HW; p += 256) {
        int lb = label[(b*512 + ((p >> 7) << 2))*512 + ((p & 127) << 2)];
        atomicAdd(&hc[lb], 1);
    }
    __syncthreads();
    if (t < L) g_cnt[b*L + t] = hc[t];
}

// ============================================================================
// Segment sums for d (set=0) and fuse (set=1): global RED.ADD.F32
// ============================================================================
__global__ void __launch_bounds__(256) stats_kernel(const float* __restrict__ dd,
                                                    const int*   __restrict__ label)
{
    __shared__ int slab[1024];
    const int t   = threadIdx.x;
    const int p0  = blockIdx.x * 1024;
    const int b   = blockIdx.y;
    const int set = blockIdx.z;
    const float* x = (set == 0) ? dd : g_fuse;
    float* s = g_sums + (set*B + b)*L*C;

    for (int i = t; i < 1024; i += 256) {
        int p = p0 + i;
        slab[i] = label[(b*512 + ((p >> 7) << 2))*512 + ((p & 127) << 2)];
    }
    __syncthreads();

    for (int c = 0; c < 128; c++) {
        const float* xp = x + ((size_t)(b*128 + c) << 14) + p0;
        for (int i = t; i < 1024; i += 256)
            atomicAdd(&s[slab[i]*128 + c], xp[i]);
    }
}

// ============================================================================
// Gate: mean (w/ base fallback) -> L2-normalize over classes -> sum -> MLP -> sigmoid
// grid (b, set), 128 threads (1 per channel)
// ============================================================================
__global__ void __launch_bounds__(128) gate_kernel(const float* __restrict__ fw1,
                                                   const float* __restrict__ fw2,
                                                   const float* __restrict__ dw1,
                                                   const float* __restrict__ dw2,
                                                   const float* __restrict__ basef,
                                                   const float* __restrict__ based)
{
    __shared__ float ss[128];
    __shared__ float sh[8];
    const int c = threadIdx.x;
    const int b = blockIdx.x, set = blockIdx.y;
    const float* sums = g_sums + (set*B + b)*L*C;
    const float* base = ((set == 0) ? based : basef) + b*L*C;
    const int*   cnt  = g_cnt + b*L;

    float suml = 0.f, sq = 0.f;
    for (int l = 0; l < L; l++) {
        int n = cnt[l];
        float m = (n > 0) ? sums[l*128 + c] / (float)n : base[l*128 + c];
        suml += m; sq += m*m;
    }
    ss[c] = suml / fmaxf(sqrtf(sq), 1e-12f);
    __syncthreads();

    if (c < 8) {
        const float* w1 = ((set == 0) ? dw1 : fw1) + c*128;
        float hsum = 0.f;
        for (int k = 0; k < 128; k++) hsum += ss[k] * w1[k];
        sh[c] = fmaxf(hsum, 0.f);
    }
    __syncthreads();

    const float* w2 = ((set == 0) ? dw2 : fw2) + c*8;
    float g = 0.f;
    #pragma unroll
    for (int o = 0; o < 8; o++) g += sh[o] * w2[o];
    g_gates[(set*B + b)*C + c] = 1.f / (1.f + expf(-g));
}

// ============================================================================
// out = fuse * gate_f[b,c] + d * gate_d[b,c]   (float4 elementwise)
// ============================================================================
__global__ void __launch_bounds__(256) out_kernel(const float* __restrict__ dd,
                                                  float* __restrict__ out)
{
    int idx = blockIdx.x * blockDim.x + threadIdx.x;   // float4 index
    int bc = idx >> 12;                                 // 4096 float4 per (b,c)
    int b = bc >> 7, c = bc & 127;
    float gf = g_gates[(B + b)*C + c];
    float gd = g_gates[b*C + c];
    float4 f4 = ((const float4*)g_fuse)[idx];
    float4 d4 = ((const float4*)dd)[idx];
    float4 o;
    o.x = f4.x*gf + d4.x*gd;
    o.y = f4.y*gf + d4.y*gd;
    o.z = f4.z*gf + d4.z*gd;
    o.w = f4.w*gf + d4.w*gd;
    ((float4*)out)[idx] = o;
}

// ============================================================================
extern "C" void kernel_launch(void* const* d_in, const int* in_sizes, int n_in,
                              void* d_out, int out_size)
{
    const float* r   = (const float*)d_in[0];
    const float* d   = (const float*)d_in[1];
    const int*   lab = (const int*)  d_in[2];
    const float* cw  = (const float*)d_in[3];
    const float* fw1 = (const float*)d_in[4];
    const float* fw2 = (const float*)d_in[5];
    const float* dw1 = (const float*)d_in[6];
    const float* dw2 = (const float*)d_in[7];
    const float* bf  = (const float*)d_in[8];
    const float* bd  = (const float*)d_in[9];
    float* out = (float*)d_out;

    zero_kernel<<<328, 256>>>();                         // 2*8*41*128 = 83968
    conv_kernel<<<dim3(128, 2, 8), 256>>>(r, d, cw);
    hist_kernel<<<8, 256>>>(lab);
    stats_kernel<<<dim3(16, 8, 2), 256>>>(d, lab);       // after conv (needs g_fuse)
    gate_kernel<<<dim3(8, 2), 128>>>(fw1, fw2, dw1, dw2, bf, bd);
    out_kernel<<<16384, 256>>>(d, out);
}

// round 6
// speedup vs baseline: 3.2939x; 3.2939x over previous
#include <cuda_runtime.h>
#include <math.h>
#include <cstdint>

#define B 8
#define C 128
#define H 128
#define W 128
#define L 41

// ---- scratch (static device globals; no allocations) ----
__device__ float    g_fuse[(size_t)B*C*H*W];      // 64 MB conv output (fp32)
__device__ uint32_t g_vin[(size_t)B*256*H*W];     // 128 MB virtual input, tf32 bits
__device__ uint32_t g_wA[72*32*128];              // weight tiles [cic*9+tap][k=32][co=128] tf32
__device__ float    g_sums[2*B*L*C];              // per-class channel sums
__device__ int      g_cnt[B*L];                   // label histogram
__device__ float    g_gates[2*B*C];               // final sigmoid gates

// ============================================================================
// helpers
// ============================================================================
__device__ __forceinline__ uint32_t f2tf32(float v){
    uint32_t u; asm("cvt.rna.tf32.f32 %0, %1;" : "=r"(u) : "f"(v)); return u;
}
__device__ __forceinline__ void mma_tf32(float* c,
        uint32_t a0, uint32_t a1, uint32_t a2, uint32_t a3,
        uint32_t b0, uint32_t b1){
    asm volatile("mma.sync.aligned.m16n8k8.row.col.f32.tf32.tf32.f32 "
                 "{%0,%1,%2,%3},{%4,%5,%6,%7},{%8,%9},{%0,%1,%2,%3};"
                 : "+f"(c[0]), "+f"(c[1]), "+f"(c[2]), "+f"(c[3])
                 : "r"(a0), "r"(a1), "r"(a2), "r"(a3), "r"(b0), "r"(b1));
}

// ============================================================================
// Virtual input prep: vin[b][ch]    = tf32(r+d)
//                     vin[b][128+ch]= tf32(r*sigmoid(d))
// ============================================================================
__global__ void __launch_bounds__(256) vin_prep(const float* __restrict__ r,
                                                const float* __restrict__ d)
{
    int idx = blockIdx.x * blockDim.x + threadIdx.x;   // float4 index
    int p  = idx & 4095;
    int bc = idx >> 12;
    int ch = bc & 127, b = bc >> 7;
    float4 r4 = ((const float4*)r)[idx];
    float4 d4 = ((const float4*)d)[idx];
    uint4 av, mv;
    av.x = f2tf32(r4.x + d4.x); av.y = f2tf32(r4.y + d4.y);
    av.z = f2tf32(r4.z + d4.z); av.w = f2tf32(r4.w + d4.w);
    mv.x = f2tf32(r4.x / (1.f + __expf(-d4.x)));
    mv.y = f2tf32(r4.y / (1.f + __expf(-d4.y)));
    mv.z = f2tf32(r4.z / (1.f + __expf(-d4.z)));
    mv.w = f2tf32(r4.w / (1.f + __expf(-d4.w)));
    int addA = (b*256 + ch)*4096 + p;
    ((uint4*)g_vin)[addA]            = av;
    ((uint4*)g_vin)[addA + 128*4096] = mv;
}

// ============================================================================
// Weight pre-transform: cw[co][civ][ky][kx] -> g_wA[(cic*9+tap)][k][co] tf32
// ============================================================================
__global__ void __launch_bounds__(256) wpre_kernel(const float* __restrict__ cw)
{
    int tile = blockIdx.x;           // 0..71
    int cic = tile / 9, tap = tile % 9;
    for (int i = threadIdx.x; i < 4096; i += 256) {
        int k = i >> 7, co = i & 127;
        float v = cw[(co*256 + cic*32 + k)*9 + tap];
        g_wA[tile*4096 + i] = f2tf32(v);
    }
}

// ============================================================================
// Conv3x3 via mma.sync tf32 implicit GEMM.
// CTA = (rowpair, cog, b): 64 co x 256 px (2 output rows). 8 warps:
//   wm = w&1 (co half of 64), wq = w>>1: rl = wq>>1 (output row), pxb = (wq&1)*64.
// Warp tile 32co x 64px: 2 m-tiles x 8 n-tiles, acc[2][8][4].
// smem: sB [4 rows][32 k][132 px] tf32 (n=0 <-> col -1), sA [9 tap][32 k][72 pad co64]
// ============================================================================
#define APAD 72
#define BROW (32*132)
#define SB_WORDS (4*BROW)                 // 16896
#define SA_WORDS (9*32*APAD)              // 20736
#define CONV_SMEM ((SB_WORDS + SA_WORDS)*4)

__global__ void __launch_bounds__(256, 1) conv_mma(const uint32_t* __restrict__ vin,
                                                   const uint32_t* __restrict__ wA)
{
    extern __shared__ uint32_t sm[];
    uint32_t* sB = sm;
    uint32_t* sA = sm + SB_WORDS;

    const int t = threadIdx.x, w = t >> 5, lane = t & 31;
    const int gid = lane >> 2, tid4 = lane & 3;
    const int rp = blockIdx.x, cog = blockIdx.y, b = blockIdx.z;
    const int h0 = rp * 2;
    const int wm = w & 1, wq = w >> 1;
    const int rl = wq >> 1, pxb = (wq & 1) * 64;

    float acc[2][8][4];
    #pragma unroll
    for (int i = 0; i < 2; i++)
        #pragma unroll
        for (int j = 0; j < 8; j++)
            #pragma unroll
            for (int q = 0; q < 4; q++) acc[i][j][q] = 0.f;

    const uint32_t* vb = vin + (size_t)b * 256 * 16384;

    for (int cic = 0; cic < 8; cic++) {
        __syncthreads();
        // ---- stage B: 4 input rows x 32 k x 132 (halo/zero pad) ----
        for (int i = t; i < SB_WORDS; i += 256) {
            int j = i / BROW;
            int rm = i - j * BROW;
            int k = rm / 132;
            int n = rm - k * 132;
            int col = n - 1;
            int row = h0 - 1 + j;
            uint32_t v = 0;
            if ((unsigned)row < 128u && (unsigned)col < 128u)
                v = vb[((cic*32 + k) << 14) + (row << 7) + col];
            sB[i] = v;
        }
        // ---- stage A: 9 taps x 32 k x 64 co (this cog's half) ----
        for (int i = t; i < 9*2048; i += 256) {
            int tap = i >> 11;
            int rm = i & 2047;
            int k = rm >> 6, co = rm & 63;
            sA[tap*32*APAD + k*APAD + co] =
                wA[((cic*9 + tap) << 12) + (k << 7) + cog*64 + co];
        }
        __syncthreads();

        #pragma unroll
        for (int tap = 0; tap < 9; tap++) {
            const int ky = tap / 3, dx = tap % 3;
            const uint32_t* sAt = sA + tap*32*APAD + wm*32;
            const uint32_t* sBt = sB + (rl + ky)*BROW + pxb + dx;
            #pragma unroll
            for (int k8 = 0; k8 < 4; k8++) {
                int kf = k8*8 + tid4;
                const uint32_t* ap = sAt + kf*APAD + gid;
                uint32_t a00 = ap[0],        a01 = ap[8];
                uint32_t a02 = ap[4*APAD],   a03 = ap[4*APAD + 8];
                uint32_t a10 = ap[16],       a11 = ap[24];
                uint32_t a12 = ap[4*APAD+16],a13 = ap[4*APAD + 24];
                const uint32_t* bp = sBt + kf*132 + gid;
                #pragma unroll
                for (int nt = 0; nt < 8; nt++) {
                    uint32_t b0 = bp[nt*8];
                    uint32_t b1 = bp[nt*8 + 4*132];
                    mma_tf32(acc[0][nt], a00, a01, a02, a03, b0, b1);
                    mma_tf32(acc[1][nt], a10, a11, a12, a13, b0, b1);
                }
            }
        }
    }

    // ---- epilogue: direct STG (32B-sector friendly float2 per quad) ----
    const int h = h0 + rl;
    #pragma unroll
    for (int mt = 0; mt < 2; mt++) {
        int co = cog*64 + wm*32 + mt*16 + gid;
        size_t base = (((size_t)b*128 + co)*128 + h)*128 + pxb + 2*tid4;
        #pragma unroll
        for (int nt = 0; nt < 8; nt++) {
            *(float2*)&g_fuse[base + nt*8] =
                make_float2(acc[mt][nt][0], acc[mt][nt][1]);
            *(float2*)&g_fuse[base + (size_t)8*16384 + nt*8] =
                make_float2(acc[mt][nt][2], acc[mt][nt][3]);
        }
    }
}

// ============================================================================
// Zero the segment-sum scratch (runs every replay)
// ============================================================================
__global__ void zero_kernel()
{
    int i = blockIdx.x * blockDim.x + threadIdx.x;
    if (i < 2*B*L*C) g_sums[i] = 0.f;
}

// ============================================================================
// Label histogram per batch (nearest-resize: label[b, 4y, 4x])
// ============================================================================
__global__ void __launch_bounds__(256) hist_kernel(const int* __restrict__ label)
{
    __shared__ int hc[L];
    int t = threadIdx.x, b = blockIdx.x;
    if (t < L) hc[t] = 0;
    __syncthreads();
    for (int p = t; p < H*W; p += 256) {
        int lb = label[(b*512 + ((p >> 7) << 2))*512 + ((p & 127) << 2)];
        atomicAdd(&hc[lb], 1);
    }
    __syncthreads();
    if (t < L) g_cnt[b*L + t] = hc[t];
}

// ============================================================================
// Segment sums as one-hot GEMM: sums[l][c] = sum_px X[c][px] * (lab[px]==l)
// grid (kc=4, b=8, set=2), 256 thr. M=128 c (warp w owns m-tile w),
// N=48 (6 n-tiles), K chunked 32 px at a time.
// ============================================================================
#define XPAD 36
#define OHS 56
__global__ void __launch_bounds__(256) stats_mma(const float* __restrict__ dd,
                                                 const int*   __restrict__ label)
{
    __shared__ uint32_t sX[128*XPAD];    // [c][px32] tf32
    __shared__ uint32_t sOH[32*OHS];     // [px][l48] tf32 one-hot
    __shared__ int slab[32];

    const int t = threadIdx.x, w = t >> 5, lane = t & 31;
    const int gid = lane >> 2, tid4 = lane & 3;
    const int kc = blockIdx.x, b = blockIdx.y, set = blockIdx.z;
    const float* X = ((set == 0) ? dd : g_fuse) + (size_t)b * 128 * 16384;
    const int k0 = kc * 4096;

    float acc[6][4];
    #pragma unroll
    for (int i = 0; i < 6; i++)
        #pragma unroll
        for (int q = 0; q < 4; q++) acc[i][q] = 0.f;

    for (int ch = 0; ch < 128; ch++) {
        int p0 = k0 + ch * 32;
        __syncthreads();
        // stage X chunk: [c][32 px]
        for (int i = t; i < 4096; i += 256) {
            int c = i >> 5, px = i & 31;
            sX[c*XPAD + px] = f2tf32(X[(size_t)c*16384 + p0 + px]);
        }
        // stage labels + one-hot
        if (t < 32) {
            int p = p0 + t;
            slab[t] = label[(b*512 + ((p >> 7) << 2))*512 + ((p & 127) << 2)];
        }
        __syncthreads();
        for (int i = t; i < 32*48; i += 256) {
            int px = i / 48, l = i - px*48;
            sOH[px*OHS + l] = (slab[px] == l) ? 0x3F800000u : 0u;
        }
        __syncthreads();

        #pragma unroll
        for (int k8 = 0; k8 < 4; k8++) {
            int kf = k8*8 + tid4;
            const uint32_t* ap = sX + (w*16 + gid)*XPAD + kf;
            uint32_t a0 = ap[0], a1 = ap[8*XPAD];
            uint32_t a2 = ap[4], a3 = ap[8*XPAD + 4];
            const uint32_t* bp = sOH + kf*OHS + gid;
            #pragma unroll
            for (int nt = 0; nt < 6; nt++) {
                uint32_t b0 = bp[nt*8];
                uint32_t b1 = bp[nt*8 + 4*OHS];
                mma_tf32(acc[nt], a0, a1, a2, a3, b0, b1);
            }
        }
    }

    // flush partials (rows c = w*16+gid (+8), cols l = nt*8 + 2*tid4 (+1))
    float* gs = g_sums + (size_t)(set*B + b) * L * C;
    int c = w*16 + gid;
    #pragma unroll
    for (int nt = 0; nt < 6; nt++) {
        int l0 = nt*8 + 2*tid4;
        if (l0 < L)     atomicAdd(&gs[l0*128 + c],       acc[nt][0]);
        if (l0 + 1 < L) atomicAdd(&gs[(l0+1)*128 + c],   acc[nt][1]);
        if (l0 < L)     atomicAdd(&gs[l0*128 + c + 8],   acc[nt][2]);
        if (l0 + 1 < L) atomicAdd(&gs[(l0+1)*128 + c+8], acc[nt][3]);
    }
}

// ============================================================================
// Gate: mean (w/ base fallback) -> L2-normalize over classes -> sum -> MLP -> sigmoid
// ============================================================================
__global__ void __launch_bounds__(128) gate_kernel(const float* __restrict__ fw1,
                                                   const float* __restrict__ fw2,
                                                   const float* __restrict__ dw1,
                                                   const float* __restrict__ dw2,
                                                   const float* __restrict__ basef,
                                                   const float* __restrict__ based)
{
    __shared__ float ss[128];
    __shared__ float sh[8];
    const int c = threadIdx.x;
    const int b = blockIdx.x, set = blockIdx.y;
    const float* sums = g_sums + (set*B + b)*L*C;
    const float* base = ((set == 0) ? based : basef) + b*L*C;
    const int*   cnt  = g_cnt + b*L;

    float suml = 0.f, sq = 0.f;
    for (int l = 0; l < L; l++) {
        int n = cnt[l];
        float m = (n > 0) ? sums[l*128 + c] / (float)n : base[l*128 + c];
        suml += m; sq += m*m;
    }
    ss[c] = suml / fmaxf(sqrtf(sq), 1e-12f);
    __syncthreads();

    if (c < 8) {
        const float* w1 = ((set == 0) ? dw1 : fw1) + c*128;
        float hsum = 0.f;
        for (int k = 0; k < 128; k++) hsum += ss[k] * w1[k];
        sh[c] = fmaxf(hsum, 0.f);
    }
    __syncthreads();

    const float* w2 = ((set == 0) ? dw2 : fw2) + c*8;
    float g = 0.f;
    #pragma unroll
    for (int o = 0; o < 8; o++) g += sh[o] * w2[o];
    g_gates[(set*B + b)*C + c] = 1.f / (1.f + expf(-g));
}

// ============================================================================
// out = fuse * gate_f[b,c] + d * gate_d[b,c]
// ============================================================================
__global__ void __launch_bounds__(256) out_kernel(const float* __restrict__ dd,
                                                  float* __restrict__ out)
{
    int idx = blockIdx.x * blockDim.x + threadIdx.x;
    int bc = idx >> 12;
    int b = bc >> 7, c = bc & 127;
    float gf = g_gates[(B + b)*C + c];
    float gd = g_gates[b*C + c];
    float4 f4 = ((const float4*)g_fuse)[idx];
    float4 d4 = ((const float4*)dd)[idx];
    float4 o;
    o.x = f4.x*gf + d4.x*gd;
    o.y = f4.y*gf + d4.y*gd;
    o.z = f4.z*gf + d4.z*gd;
    o.w = f4.w*gf + d4.w*gd;
    ((float4*)out)[idx] = o;
}

// ============================================================================
extern "C" void kernel_launch(void* const* d_in, const int* in_sizes, int n_in,
                              void* d_out, int out_size)
{
    const float* r   = (const float*)d_in[0];
    const float* d   = (const float*)d_in[1];
    const int*   lab = (const int*)  d_in[2];
    const float* cw  = (const float*)d_in[3];
    const float* fw1 = (const float*)d_in[4];
    const float* fw2 = (const float*)d_in[5];
    const float* dw1 = (const float*)d_in[6];
    const float* dw2 = (const float*)d_in[7];
    const float* bf  = (const float*)d_in[8];
    const float* bd  = (const float*)d_in[9];
    float* out = (float*)d_out;

    cudaFuncSetAttribute(conv_mma, cudaFuncAttributeMaxDynamicSharedMemorySize, CONV_SMEM);

    uint32_t* vin_ptr = nullptr;
    uint32_t* wA_ptr = nullptr;
    cudaGetSymbolAddress((void**)&vin_ptr, g_vin);
    cudaGetSymbolAddress((void**)&wA_ptr,  g_wA);

    wpre_kernel<<<72, 256>>>(cw);
    vin_prep<<<16384, 256>>>(r, d);
    zero_kernel<<<328, 256>>>();
    conv_mma<<<dim3(64, 2, 8), 256, CONV_SMEM>>>(vin_ptr, wA_ptr);
    hist_kernel<<<8, 256>>>(lab);
    stats_mma<<<dim3(4, 8, 2), 256>>>(d, lab);
    gate_kernel<<<dim3(8, 2), 128>>>(fw1, fw2, dw1, dw2, bf, bd);
    out_kernel<<<16384, 256>>>(d, out);
}

// round 9
// speedup vs baseline: 14.0318x; 4.2599x over previous
#include <cuda_runtime.h>
#include <cuda_fp16.h>
#include <math.h>
#include <cstdint>

#define B 8
#define C 128
#define L 41

// ---- scratch (static device globals; no allocations) ----
__device__ float  g_fuse[(size_t)B*C*128*128];     // 64 MB conv output (fp32)
__device__ __half g_vin[(size_t)B*128*128*256];    // 64 MB, [b][row][col][civ] half
__device__ __half g_wH[72*128*32];                 // [tile][co 128][k 32] half
__device__ float  g_sums[2*B*L*C];
__device__ int    g_cnt[B*L];
__device__ float  g_gates[2*B*C];

// ============================================================================
// helpers
// ============================================================================
__device__ __forceinline__ void mma_f16(float* c,
        uint32_t a0, uint32_t a1, uint32_t a2, uint32_t a3,
        uint32_t b0, uint32_t b1){
    asm volatile("mma.sync.aligned.m16n8k16.row.col.f32.f16.f16.f32 "
                 "{%0,%1,%2,%3},{%4,%5,%6,%7},{%8,%9},{%0,%1,%2,%3};"
                 : "+f"(c[0]), "+f"(c[1]), "+f"(c[2]), "+f"(c[3])
                 : "r"(a0), "r"(a1), "r"(a2), "r"(a3), "r"(b0), "r"(b1));
}
__device__ __forceinline__ uint32_t h2_u32(__half2 h){
    return *(uint32_t*)&h;
}

// ============================================================================
// Virtual input prep, channel-contiguous transposed layout:
//   g_vin[b][row][col][ch]     = half(r+d)            ch in [0,128)
//   g_vin[b][row][col][128+ch] = half(r*sigmoid(d))
// Block = (row, b), 256 thr: t -> cp = t&63 (channel pair 2cp,2cp+1),
// seg = t>>6 (32-col segment). Writes: lanes = consecutive cp at fixed col
// -> 128B coalesced half2 runs. Reads: per-thread float4 runs (L1-friendly).
// ============================================================================
__global__ void __launch_bounds__(256) vin_prep(const float* __restrict__ r,
                                                const float* __restrict__ d)
{
    const int row = blockIdx.x, b = blockIdx.y;
    const int t = threadIdx.x;
    const int cp = t & 63, seg = t >> 6;
    const size_t in0 = (((size_t)b*128 + 2*cp)*128 + row)*128 + seg*32;
    const float4* R0 = (const float4*)(r + in0);
    const float4* R1 = (const float4*)(r + in0 + 16384);
    const float4* D0 = (const float4*)(d + in0);
    const float4* D1 = (const float4*)(d + in0 + 16384);
    __half* vout = g_vin + (((size_t)b*128 + row)*128)*256;

    #pragma unroll
    for (int i4 = 0; i4 < 8; i4++) {
        float4 ra = R0[i4], rb = R1[i4];
        float4 da = D0[i4], db = D1[i4];
        float av0[4] = {ra.x+da.x, ra.y+da.y, ra.z+da.z, ra.w+da.w};
        float av1[4] = {rb.x+db.x, rb.y+db.y, rb.z+db.z, rb.w+db.w};
        float mv0[4] = {ra.x/(1.f+__expf(-da.x)), ra.y/(1.f+__expf(-da.y)),
                        ra.z/(1.f+__expf(-da.z)), ra.w/(1.f+__expf(-da.w))};
        float mv1[4] = {rb.x/(1.f+__expf(-db.x)), rb.y/(1.f+__expf(-db.y)),
                        rb.z/(1.f+__expf(-db.z)), rb.w/(1.f+__expf(-db.w))};
        #pragma unroll
        for (int u = 0; u < 4; u++) {
            int col = seg*32 + i4*4 + u;
            *(__half2*)(vout + (size_t)col*256 + 2*cp)       = __floats2half2_rn(av0[u], av1[u]);
            *(__half2*)(vout + (size_t)col*256 + 128 + 2*cp) = __floats2half2_rn(mv0[u], mv1[u]);
        }
    }
}

// ============================================================================
// Weight pre-transform: cw[co][civ][tap] -> g_wH[(cic*9+tap)][co][k] half
// ============================================================================
__global__ void __launch_bounds__(256) wpre_kernel(const float* __restrict__ cw)
{
    int tile = blockIdx.x;               // 0..71
    int cic = tile / 9, tap = tile % 9;
    for (int i = threadIdx.x; i < 4096; i += 256) {
        int co = i >> 5, k = i & 31;
        float v = cw[(co*256 + cic*32 + k)*9 + tap];
        g_wH[tile*4096 + co*32 + k] = __float2half_rn(v);
    }
}

// ============================================================================
// Conv3x3 via mma.sync fp16 m16n8k16 implicit GEMM.
// CTA = (rowpair, cog, b): 64 co x 256 px (2 output rows). 8 warps.
// smem: sB [4 row][132 px][40 kpad] halves, sA [9 tap][64 co][40 kpad] halves.
// 88.3 KB -> 2 CTAs/SM.
// ============================================================================
#define PXS 40
#define SB_H (4*132*PXS)     // 21120 halves
#define SA_H (9*64*PXS)      // 23040 halves
#define CONV_SMEM ((SB_H + SA_H)*2)

__global__ void __launch_bounds__(256, 2) conv_mma(const __half* __restrict__ vin,
                                                   const __half* __restrict__ wH)
{
    extern __shared__ __half sm[];
    __half* sB = sm;
    __half* sA = sm + SB_H;

    const int t = threadIdx.x, w = t >> 5, lane = t & 31;
    const int gid = lane >> 2, tid4 = lane & 3;
    const int rp = blockIdx.x, cog = blockIdx.y, b = blockIdx.z;
    const int h0 = rp * 2;
    const int wm = w & 1, wq = w >> 1;
    const int rl = wq >> 1, pxb = (wq & 1) * 64;

    float acc[2][8][4];
    #pragma unroll
    for (int i = 0; i < 2; i++)
        #pragma unroll
        for (int j = 0; j < 8; j++)
            #pragma unroll
            for (int q = 0; q < 4; q++) acc[i][j][q] = 0.f;

    const __half* vb = vin + (size_t)b * 128 * 128 * 256;

    for (int cic = 0; cic < 8; cic++) {
        __syncthreads();
        // ---- stage B: 4 rows x 132 px x 32k as uint4 (8 halves) ----
        for (int i = t; i < 2112; i += 256) {
            int j = i / 528;
            int rm = i - j * 528;
            int px = rm >> 2, kq = rm & 3;
            int col = px - 1, row = h0 - 1 + j;
            uint4 v = make_uint4(0, 0, 0, 0);
            if ((unsigned)row < 128u && (unsigned)col < 128u)
                v = *(const uint4*)(vb + ((size_t)row*128 + col)*256 + cic*32 + kq*8);
            *(uint4*)(sB + (j*132 + px)*PXS + kq*8) = v;
        }
        // ---- stage A: 9 taps x 64 co x 32k ----
        for (int i = t; i < 2304; i += 256) {
            int tap = i >> 8;
            int rm = i & 255;
            int c64 = rm >> 2, kq = rm & 3;
            uint4 v = *(const uint4*)(wH + ((size_t)(cic*9 + tap)*128 + cog*64 + c64)*32 + kq*8);
            *(uint4*)(sA + (tap*64 + c64)*PXS + kq*8) = v;
        }
        __syncthreads();

        #pragma unroll
        for (int tap = 0; tap < 9; tap++) {
            const int ky = tap / 3, dx = tap % 3;
            const __half* At = sA + (tap*64 + wm*32) * PXS;
            const __half* Bt = sB + ((rl + ky)*132 + pxb + dx) * PXS;
            #pragma unroll
            for (int ks = 0; ks < 2; ks++) {
                const int k0 = ks*16 + 2*tid4;
                uint32_t a[2][4];
                #pragma unroll
                for (int mt = 0; mt < 2; mt++) {
                    const __half* ap = At + (mt*16 + gid)*PXS + k0;
                    a[mt][0] = *(const uint32_t*)(ap);
                    a[mt][1] = *(const uint32_t*)(ap + 8*PXS);
                    a[mt][2] = *(const uint32_t*)(ap + 8);
                    a[mt][3] = *(const uint32_t*)(ap + 8*PXS + 8);
                }
                #pragma unroll
                for (int nt = 0; nt < 8; nt++) {
                    const __half* bp = Bt + (nt*8 + gid)*PXS + k0;
                    uint32_t b0 = *(const uint32_t*)(bp);
                    uint32_t b1 = *(const uint32_t*)(bp + 8);
                    mma_f16(acc[0][nt], a[0][0], a[0][1], a[0][2], a[0][3], b0, b1);
                    mma_f16(acc[1][nt], a[1][0], a[1][1], a[1][2], a[1][3], b0, b1);
                }
            }
        }
    }

    // ---- epilogue: direct STG ----
    const int h = h0 + rl;
    #pragma unroll
    for (int mt = 0; mt < 2; mt++) {
        int co = cog*64 + wm*32 + mt*16 + gid;
        size_t base = (((size_t)b*128 + co)*128 + h)*128 + pxb + 2*tid4;
        #pragma unroll
        for (int nt = 0; nt < 8; nt++) {
            *(float2*)&g_fuse[base + nt*8] =
                make_float2(acc[mt][nt][0], acc[mt][nt][1]);
            *(float2*)&g_fuse[base + (size_t)8*16384 + nt*8] =
                make_float2(acc[mt][nt][2], acc[mt][nt][3]);
        }
    }
}

// ============================================================================
__global__ void zero_kernel()
{
    int i = blockIdx.x * blockDim.x + threadIdx.x;
    if (i < 2*B*L*C) g_sums[i] = 0.f;
}

// ============================================================================
__global__ void __launch_bounds__(256) hist_kernel(const int* __restrict__ label)
{
    __shared__ int hc[L];
    int t = threadIdx.x, b = blockIdx.x;
    if (t < L) hc[t] = 0;
    __syncthreads();
    for (int p = t; p < 16384; p += 256) {
        int lb = label[(b*512 + ((p >> 7) << 2))*512 + ((p & 127) << 2)];
        atomicAdd(&hc[lb], 1);
    }
    __syncthreads();
    if (t < L) g_cnt[b*L + t] = hc[t];
}

// ============================================================================
// Segment sums as one-hot GEMM (fp16 m16n8k16), smem-free:
// A-fragments = direct float2 LDG from X (->half2), B one-hot built in regs
// from shfl'd labels. grid (kc=16, b=8, set=2), 256 thr; warp w owns
// m-rows w*16..w*16+15; N=48 (6 n-tiles); 32 chunks of 32 px.
// ============================================================================
__global__ void __launch_bounds__(256) stats_mma(const float* __restrict__ dd,
                                                 const int*   __restrict__ label)
{
    const int t = threadIdx.x, w = t >> 5, lane = t & 31;
    const int gid = lane >> 2, tid4 = lane & 3;
    const int kc = blockIdx.x, b = blockIdx.y, set = blockIdx.z;
    const float* X = ((set == 0) ? dd : g_fuse) + (size_t)b * 128 * 16384;
    const int c0 = w * 16;

    float acc[6][4];
    #pragma unroll
    for (int i = 0; i < 6; i++)
        #pragma unroll
        for (int q = 0; q < 4; q++) acc[i][q] = 0.f;

    for (int chunk = 0; chunk < 32; chunk++) {
        const int p0 = kc*1024 + chunk*32;
        const int p = p0 + lane;
        const int ll = label[(b*512 + ((p >> 7) << 2))*512 + ((p & 127) << 2)];

        #pragma unroll
        for (int ks = 0; ks < 2; ks++) {
            const int koff = ks*16 + 2*tid4;
            const float* xr = X + (size_t)(c0 + gid)*16384 + p0 + koff;
            float2 f0 = *(const float2*)(xr);
            float2 f1 = *(const float2*)(xr + (size_t)8*16384);
            float2 f2 = *(const float2*)(xr + 8);
            float2 f3 = *(const float2*)(xr + (size_t)8*16384 + 8);
            uint32_t a0 = h2_u32(__floats2half2_rn(f0.x, f0.y));
            uint32_t a1 = h2_u32(__floats2half2_rn(f1.x, f1.y));
            uint32_t a2 = h2_u32(__floats2half2_rn(f2.x, f2.y));
            uint32_t a3 = h2_u32(__floats2half2_rn(f3.x, f3.y));

            int l0 = __shfl_sync(0xffffffffu, ll, koff);
            int l1 = __shfl_sync(0xffffffffu, ll, koff + 1);
            int l2 = __shfl_sync(0xffffffffu, ll, koff + 8);
            int l3 = __shfl_sync(0xffffffffu, ll, koff + 9);

            #pragma unroll
            for (int nt = 0; nt < 6; nt++) {
                int cls = nt*8 + gid;
                uint32_t b0 = ((l0 == cls) ? 0x3C00u : 0u) | ((l1 == cls) ? 0x3C000000u : 0u);
                uint32_t b1 = ((l2 == cls) ? 0x3C00u : 0u) | ((l3 == cls) ? 0x3C000000u : 0u);
                mma_f16(acc[nt], a0, a1, a2, a3, b0, b1);
            }
        }
    }

    float* gs = g_sums + (size_t)(set*B + b) * L * C;
    int c = c0 + gid;
    #pragma unroll
    for (int nt = 0; nt < 6; nt++) {
        int l0 = nt*8 + 2*tid4;
        if (l0 < L)     atomicAdd(&gs[l0*128 + c],        acc[nt][0]);
        if (l0 + 1 < L) atomicAdd(&gs[(l0+1)*128 + c],    acc[nt][1]);
        if (l0 < L)     atomicAdd(&gs[l0*128 + c + 8],    acc[nt][2]);
        if (l0 + 1 < L) atomicAdd(&gs[(l0+1)*128 + c + 8], acc[nt][3]);
    }
}

// ============================================================================
__global__ void __launch_bounds__(128) gate_kernel(const float* __restrict__ fw1,
                                                   const float* __restrict__ fw2,
                                                   const float* __restrict__ dw1,
                                                   const float* __restrict__ dw2,
                                                   const float* __restrict__ basef,
                                                   const float* __restrict__ based)
{
    __shared__ float ss[128];
    __shared__ float sh[8];
    const int c = threadIdx.x;
    const int b = blockIdx.x, set = blockIdx.y;
    const float* sums = g_sums + (set*B + b)*L*C;
    const float* base = ((set == 0) ? based : basef) + b*L*C;
    const int*   cnt  = g_cnt + b*L;

    float suml = 0.f, sq = 0.f;
    for (int l = 0; l < L; l++) {
        int n = cnt[l];
        float m = (n > 0) ? sums[l*128 + c] / (float)n : base[l*128 + c];
        suml += m; sq += m*m;
    }
    ss[c] = suml / fmaxf(sqrtf(sq), 1e-12f);
    __syncthreads();

    if (c < 8) {
        const float* w1 = ((set == 0) ? dw1 : fw1) + c*128;
        float hsum = 0.f;
        for (int k = 0; k < 128; k++) hsum += ss[k] * w1[k];
        sh[c] = fmaxf(hsum, 0.f);
    }
    __syncthreads();

    const float* w2 = ((set == 0) ? dw2 : fw2) + c*8;
    float g = 0.f;
    #pragma unroll
    for (int o = 0; o < 8; o++) g += sh[o] * w2[o];
    g_gates[(set*B + b)*C + c] = 1.f / (1.f + expf(-g));
}

// ============================================================================
__global__ void __launch_bounds__(256) out_kernel(const float* __restrict__ dd,
                                                  float* __restrict__ out)
{
    int idx = blockIdx.x * blockDim.x + threadIdx.x;
    int bc = idx >> 12;
    int b = bc >> 7, c = bc & 127;
    float gf = g_gates[(B + b)*C + c];
    float gd = g_gates[b*C + c];
    float4 f4 = ((const float4*)g_fuse)[idx];
    float4 d4 = ((const float4*)dd)[idx];
    float4 o;
    o.x = f4.x*gf + d4.x*gd;
    o.y = f4.y*gf + d4.y*gd;
    o.z = f4.z*gf + d4.z*gd;
    o.w = f4.w*gf + d4.w*gd;
    ((float4*)out)[idx] = o;
}

// ============================================================================
extern "C" void kernel_launch(void* const* d_in, const int* in_sizes, int n_in,
                              void* d_out, int out_size)
{
    const float* r   = (const float*)d_in[0];
    const float* d   = (const float*)d_in[1];
    const int*   lab = (const int*)  d_in[2];
    const float* cw  = (const float*)d_in[3];
    const float* fw1 = (const float*)d_in[4];
    const float* fw2 = (const float*)d_in[5];
    const float* dw1 = (const float*)d_in[6];
    const float* dw2 = (const float*)d_in[7];
    const float* bf  = (const float*)d_in[8];
    const float* bd  = (const float*)d_in[9];
    float* out = (float*)d_out;

    cudaFuncSetAttribute(conv_mma, cudaFuncAttributeMaxDynamicSharedMemorySize, CONV_SMEM);

    __half* vin_ptr = nullptr;
    __half* wH_ptr = nullptr;
    cudaGetSymbolAddress((void**)&vin_ptr, g_vin);
    cudaGetSymbolAddress((void**)&wH_ptr,  g_wH);

    wpre_kernel<<<72, 256>>>(cw);
    vin_prep<<<dim3(128, 8), 256>>>(r, d);
    zero_kernel<<<328, 256>>>();
    conv_mma<<<dim3(64, 2, 8), 256, CONV_SMEM>>>(vin_ptr, wH_ptr);
    hist_kernel<<<8, 256>>>(lab);
    stats_mma<<<dim3(16, 8, 2), 256>>>(d, lab);
    gate_kernel<<<dim3(8, 2), 128>>>(fw1, fw2, dw1, dw2, bf, bd);
    out_kernel<<<16384, 256>>>(d, out);
}

// round 10
// speedup vs baseline: 14.4170x; 1.0274x over previous
#include <cuda_runtime.h>
#include <cuda_fp16.h>
#include <math.h>
#include <cstdint>

#define B 8
#define C 128
#define L 41

// ---- scratch (static device globals; no allocations) ----
__device__ float  g_fuse[(size_t)B*C*128*128];     // 64 MB conv output (fp32)
__device__ __half g_vin[(size_t)B*128*128*256];    // 64 MB, [b][row][col][civ] half
__device__ __half g_wH[72*128*32];                 // [tile][co 128][k 32] half
__device__ float  g_sums[2*B*L*C];
__device__ int    g_cnt[B*L];
__device__ float  g_gates[2*B*C];

// ============================================================================
// helpers
// ============================================================================
__device__ __forceinline__ void mma_f16(float* c,
        uint32_t a0, uint32_t a1, uint32_t a2, uint32_t a3,
        uint32_t b0, uint32_t b1){
    asm volatile("mma.sync.aligned.m16n8k16.row.col.f32.f16.f16.f32 "
                 "{%0,%1,%2,%3},{%4,%5,%6,%7},{%8,%9},{%0,%1,%2,%3};"
                 : "+f"(c[0]), "+f"(c[1]), "+f"(c[2]), "+f"(c[3])
                 : "r"(a0), "r"(a1), "r"(a2), "r"(a3), "r"(b0), "r"(b1));
}
__device__ __forceinline__ void ldsm_x4(uint32_t& r0, uint32_t& r1,
                                        uint32_t& r2, uint32_t& r3, uint32_t addr){
    asm volatile("ldmatrix.sync.aligned.m8n8.x4.shared.b16 {%0,%1,%2,%3}, [%4];"
                 : "=r"(r0), "=r"(r1), "=r"(r2), "=r"(r3) : "r"(addr));
}
__device__ __forceinline__ uint32_t h2_u32(__half2 h){
    return *(uint32_t*)&h;
}

// ============================================================================
// Virtual input prep, channel-contiguous transposed layout:
//   g_vin[b][row][col][ch]     = half(r+d)            ch in [0,128)
//   g_vin[b][row][col][128+ch] = half(r*sigmoid(d))
// ============================================================================
__global__ void __launch_bounds__(256) vin_prep(const float* __restrict__ r,
                                                const float* __restrict__ d)
{
    const int row = blockIdx.x, b = blockIdx.y;
    const int t = threadIdx.x;
    const int cp = t & 63, seg = t >> 6;
    const size_t in0 = (((size_t)b*128 + 2*cp)*128 + row)*128 + seg*32;
    const float4* R0 = (const float4*)(r + in0);
    const float4* R1 = (const float4*)(r + in0 + 16384);
    const float4* D0 = (const float4*)(d + in0);
    const float4* D1 = (const float4*)(d + in0 + 16384);
    __half* vout = g_vin + (((size_t)b*128 + row)*128)*256;

    #pragma unroll
    for (int i4 = 0; i4 < 8; i4++) {
        float4 ra = R0[i4], rb = R1[i4];
        float4 da = D0[i4], db = D1[i4];
        float av0[4] = {ra.x+da.x, ra.y+da.y, ra.z+da.z, ra.w+da.w};
        float av1[4] = {rb.x+db.x, rb.y+db.y, rb.z+db.z, rb.w+db.w};
        float mv0[4] = {ra.x/(1.f+__expf(-da.x)), ra.y/(1.f+__expf(-da.y)),
                        ra.z/(1.f+__expf(-da.z)), ra.w/(1.f+__expf(-da.w))};
        float mv1[4] = {rb.x/(1.f+__expf(-db.x)), rb.y/(1.f+__expf(-db.y)),
                        rb.z/(1.f+__expf(-db.z)), rb.w/(1.f+__expf(-db.w))};
        #pragma unroll
        for (int u = 0; u < 4; u++) {
            int col = seg*32 + i4*4 + u;
            *(__half2*)(vout + (size_t)col*256 + 2*cp)       = __floats2half2_rn(av0[u], av1[u]);
            *(__half2*)(vout + (size_t)col*256 + 128 + 2*cp) = __floats2half2_rn(mv0[u], mv1[u]);
        }
    }
}

// ============================================================================
// Weight pre-transform: cw[co][civ][tap] -> g_wH[(cic*9+tap)][co][k] half
// ============================================================================
__global__ void __launch_bounds__(256) wpre_kernel(const float* __restrict__ cw)
{
    int tile = blockIdx.x;               // 0..71
    int cic = tile / 9, tap = tile % 9;
    for (int i = threadIdx.x; i < 4096; i += 256) {
        int co = i >> 5, k = i & 31;
        float v = cw[(co*256 + cic*32 + k)*9 + tap];
        g_wH[tile*4096 + co*32 + k] = __float2half_rn(v);
    }
}

// ============================================================================
// Conv3x3 via mma.sync fp16 m16n8k16 implicit GEMM + ldmatrix fragments.
// CTA = (rowpair, cog, b): 64 co x 256 px (2 output rows). 8 warps.
// smem: sB [4 row][132 px][40 kpad] halves, sA [9 tap][64 co][40 kpad] halves.
// 88.3 KB -> 2 CTAs/SM. PXS=40 (80B) stride keeps ldmatrix conflict-free.
// ============================================================================
#define PXS 40
#define SB_H (4*132*PXS)     // 21120 halves
#define SA_H (9*64*PXS)      // 23040 halves
#define CONV_SMEM ((SB_H + SA_H)*2)

__global__ void __launch_bounds__(256, 2) conv_mma(const __half* __restrict__ vin,
                                                   const __half* __restrict__ wH)
{
    extern __shared__ __half sm[];
    __half* sB = sm;
    __half* sA = sm + SB_H;

    const int t = threadIdx.x, w = t >> 5, lane = t & 31;
    const int gid = lane >> 2, tid4 = lane & 3;
    const int rp = blockIdx.x, cog = blockIdx.y, b = blockIdx.z;
    const int h0 = rp * 2;
    const int wm = w & 1, wq = w >> 1;
    const int rl = wq >> 1, pxb = (wq & 1) * 64;

    // ldmatrix lane->address maps
    const int arow = lane & 15;                       // A: row within m16
    const int akof = ((lane >> 4) & 1) * 8;           // A: k offset 0/8
    const int brow = (lane & 7) + ((lane & 16) ? 8 : 0); // B: px row within n16
    const int bkof = ((lane >> 3) & 1) * 8;           // B: k offset 0/8

    const uint32_t sA_u = (uint32_t)__cvta_generic_to_shared(sA);
    const uint32_t sB_u = (uint32_t)__cvta_generic_to_shared(sB);
    const uint32_t aoff = sA_u + (uint32_t)(((wm*32 + arow)*PXS + akof) * 2);
    const uint32_t boff = sB_u + (uint32_t)(((pxb + brow)*PXS + bkof) * 2);

    float acc[2][8][4];
    #pragma unroll
    for (int i = 0; i < 2; i++)
        #pragma unroll
        for (int j = 0; j < 8; j++)
            #pragma unroll
            for (int q = 0; q < 4; q++) acc[i][j][q] = 0.f;

    const __half* vb = vin + (size_t)b * 128 * 128 * 256;

    for (int cic = 0; cic < 8; cic++) {
        __syncthreads();
        // ---- stage B: 4 rows x 132 px x 32k as uint4 (8 halves) ----
        for (int i = t; i < 2112; i += 256) {
            int j = i / 528;
            int rm = i - j * 528;
            int px = rm >> 2, kq = rm & 3;
            int col = px - 1, row = h0 - 1 + j;
            uint4 v = make_uint4(0, 0, 0, 0);
            if ((unsigned)row < 128u && (unsigned)col < 128u)
                v = *(const uint4*)(vb + ((size_t)row*128 + col)*256 + cic*32 + kq*8);
            *(uint4*)(sB + (j*132 + px)*PXS + kq*8) = v;
        }
        // ---- stage A: 9 taps x 64 co x 32k ----
        for (int i = t; i < 2304; i += 256) {
            int tap = i >> 8;
            int rm = i & 255;
            int c64 = rm >> 2, kq = rm & 3;
            uint4 v = *(const uint4*)(wH + ((size_t)(cic*9 + tap)*128 + cog*64 + c64)*32 + kq*8);
            *(uint4*)(sA + (tap*64 + c64)*PXS + kq*8) = v;
        }
        __syncthreads();

        #pragma unroll
        for (int tap = 0; tap < 9; tap++) {
            const int ky = tap / 3, dx = tap % 3;
            const uint32_t at = aoff + (uint32_t)(tap*64*PXS*2);
            const uint32_t bt = boff + (uint32_t)((((rl + ky)*132 + dx)*PXS)*2);
            #pragma unroll
            for (int ks = 0; ks < 2; ks++) {
                uint32_t a0[4], a1[4];
                ldsm_x4(a0[0], a0[1], a0[2], a0[3], at + ks*32);
                ldsm_x4(a1[0], a1[1], a1[2], a1[3], at + 16*PXS*2 + ks*32);
                #pragma unroll
                for (int q = 0; q < 4; q++) {
                    uint32_t bb[4];
                    ldsm_x4(bb[0], bb[1], bb[2], bb[3], bt + q*16*PXS*2 + ks*32);
                    mma_f16(acc[0][2*q],   a0[0], a0[1], a0[2], a0[3], bb[0], bb[1]);
                    mma_f16(acc[1][2*q],   a1[0], a1[1], a1[2], a1[3], bb[0], bb[1]);
                    mma_f16(acc[0][2*q+1], a0[0], a0[1], a0[2], a0[3], bb[2], bb[3]);
                    mma_f16(acc[1][2*q+1], a1[0], a1[1], a1[2], a1[3], bb[2], bb[3]);
                }
            }
        }
    }

    // ---- epilogue: direct STG ----
    const int h = h0 + rl;
    #pragma unroll
    for (int mt = 0; mt < 2; mt++) {
        int co = cog*64 + wm*32 + mt*16 + gid;
        size_t base = (((size_t)b*128 + co)*128 + h)*128 + pxb + 2*tid4;
        #pragma unroll
        for (int nt = 0; nt < 8; nt++) {
            *(float2*)&g_fuse[base + nt*8] =
                make_float2(acc[mt][nt][0], acc[mt][nt][1]);
            *(float2*)&g_fuse[base + (size_t)8*16384 + nt*8] =
                make_float2(acc[mt][nt][2], acc[mt][nt][3]);
        }
    }
}

// ============================================================================
__global__ void zero_kernel()
{
    int i = blockIdx.x * blockDim.x + threadIdx.x;
    if (i < 2*B*L*C) g_sums[i] = 0.f;
}

// ============================================================================
__global__ void __launch_bounds__(256) hist_kernel(const int* __restrict__ label)
{
    __shared__ int hc[L];
    int t = threadIdx.x, b = blockIdx.x;
    if (t < L) hc[t] = 0;
    __syncthreads();
    for (int p = t; p < 16384; p += 256) {
        int lb = label[(b*512 + ((p >> 7) << 2))*512 + ((p & 127) << 2)];
        atomicAdd(&hc[lb], 1);
    }
    __syncthreads();
    if (t < L) g_cnt[b*L + t] = hc[t];
}

// ============================================================================
// Segment sums as one-hot GEMM (fp16 m16n8k16), smem-free.
// ============================================================================
__global__ void __launch_bounds__(256) stats_mma(const float* __restrict__ dd,
                                                 const int*   __restrict__ label)
{
    const int t = threadIdx.x, w = t >> 5, lane = t & 31;
    const int gid = lane >> 2, tid4 = lane & 3;
    const int kc = blockIdx.x, b = blockIdx.y, set = blockIdx.z;
    const float* X = ((set == 0) ? dd : g_fuse) + (size_t)b * 128 * 16384;
    const int c0 = w * 16;

    float acc[6][4];
    #pragma unroll
    for (int i = 0; i < 6; i++)
        #pragma unroll
        for (int q = 0; q < 4; q++) acc[i][q] = 0.f;

    for (int chunk = 0; chunk < 32; chunk++) {
        const int p0 = kc*1024 + chunk*32;
        const int p = p0 + lane;
        const int ll = label[(b*512 + ((p >> 7) << 2))*512 + ((p & 127) << 2)];

        #pragma unroll
        for (int ks = 0; ks < 2; ks++) {
            const int koff = ks*16 + 2*tid4;
            const float* xr = X + (size_t)(c0 + gid)*16384 + p0 + koff;
            float2 f0 = *(const float2*)(xr);
            float2 f1 = *(const float2*)(xr + (size_t)8*16384);
            float2 f2 = *(const float2*)(xr + 8);
            float2 f3 = *(const float2*)(xr + (size_t)8*16384 + 8);
            uint32_t a0 = h2_u32(__floats2half2_rn(f0.x, f0.y));
            uint32_t a1 = h2_u32(__floats2half2_rn(f1.x, f1.y));
            uint32_t a2 = h2_u32(__floats2half2_rn(f2.x, f2.y));
            uint32_t a3 = h2_u32(__floats2half2_rn(f3.x, f3.y));

            int l0 = __shfl_sync(0xffffffffu, ll, koff);
            int l1 = __shfl_sync(0xffffffffu, ll, koff + 1);
            int l2 = __shfl_sync(0xffffffffu, ll, koff + 8);
            int l3 = __shfl_sync(0xffffffffu, ll, koff + 9);

            #pragma unroll
            for (int nt = 0; nt < 6; nt++) {
                int cls = nt*8 + gid;
                uint32_t b0 = ((l0 == cls) ? 0x3C00u : 0u) | ((l1 == cls) ? 0x3C000000u : 0u);
                uint32_t b1 = ((l2 == cls) ? 0x3C00u : 0u) | ((l3 == cls) ? 0x3C000000u : 0u);
                mma_f16(acc[nt], a0, a1, a2, a3, b0, b1);
            }
        }
    }

    float* gs = g_sums + (size_t)(set*B + b) * L * C;
    int c = c0 + gid;
    #pragma unroll
    for (int nt = 0; nt < 6; nt++) {
        int l0 = nt*8 + 2*tid4;
        if (l0 < L)     atomicAdd(&gs[l0*128 + c],        acc[nt][0]);
        if (l0 + 1 < L) atomicAdd(&gs[(l0+1)*128 + c],    acc[nt][1]);
        if (l0 < L)     atomicAdd(&gs[l0*128 + c + 8],    acc[nt][2]);
        if (l0 + 1 < L) atomicAdd(&gs[(l0+1)*128 + c + 8], acc[nt][3]);
    }
}

// ============================================================================
__global__ void __launch_bounds__(128) gate_kernel(const float* __restrict__ fw1,
                                                   const float* __restrict__ fw2,
                                                   const float* __restrict__ dw1,
                                                   const float* __restrict__ dw2,
                                                   const float* __restrict__ basef,
                                                   const float* __restrict__ based)
{
    __shared__ float ss[128];
    __shared__ float sh[8];
    const int c = threadIdx.x;
    const int b = blockIdx.x, set = blockIdx.y;
    const float* sums = g_sums + (set*B + b)*L*C;
    const float* base = ((set == 0) ? based : basef) + b*L*C;
    const int*   cnt  = g_cnt + b*L;

    float suml = 0.f, sq = 0.f;
    for (int l = 0; l < L; l++) {
        int n = cnt[l];
        float m = (n > 0) ? sums[l*128 + c] / (float)n : base[l*128 + c];
        suml += m; sq += m*m;
    }
    ss[c] = suml / fmaxf(sqrtf(sq), 1e-12f);
    __syncthreads();

    if (c < 8) {
        const float* w1 = ((set == 0) ? dw1 : fw1) + c*128;
        float hsum = 0.f;
        for (int k = 0; k < 128; k++) hsum += ss[k] * w1[k];
        sh[c] = fmaxf(hsum, 0.f);
    }
    __syncthreads();

    const float* w2 = ((set == 0) ? dw2 : fw2) + c*8;
    float g = 0.f;
    #pragma unroll
    for (int o = 0; o < 8; o++) g += sh[o] * w2[o];
    g_gates[(set*B + b)*C + c] = 1.f / (1.f + expf(-g));
}

// ============================================================================
__global__ void __launch_bounds__(256) out_kernel(const float* __restrict__ dd,
                                                  float* __restrict__ out)
{
    int idx = blockIdx.x * blockDim.x + threadIdx.x;
    int bc = idx >> 12;
    int b = bc >> 7, c = bc & 127;
    float gf = g_gates[(B + b)*C + c];
    float gd = g_gates[b*C + c];
    float4 f4 = ((const float4*)g_fuse)[idx];
    float4 d4 = ((const float4*)dd)[idx];
    float4 o;
    o.x = f4.x*gf + d4.x*gd;
    o.y = f4.y*gf + d4.y*gd;
    o.z = f4.z*gf + d4.z*gd;
    o.w = f4.w*gf + d4.w*gd;
    ((float4*)out)[idx] = o;
}

// ============================================================================
extern "C" void kernel_launch(void* const* d_in, const int* in_sizes, int n_in,
                              void* d_out, int out_size)
{
    const float* r   = (const float*)d_in[0];
    const float* d   = (const float*)d_in[1];
    const int*   lab = (const int*)  d_in[2];
    const float* cw  = (const float*)d_in[3];
    const float* fw1 = (const float*)d_in[4];
    const float* fw2 = (const float*)d_in[5];
    const float* dw1 = (const float*)d_in[6];
    const float* dw2 = (const float*)d_in[7];
    const float* bf  = (const float*)d_in[8];
    const float* bd  = (const float*)d_in[9];
    float* out = (float*)d_out;

    cudaFuncSetAttribute(conv_mma, cudaFuncAttributeMaxDynamicSharedMemorySize, CONV_SMEM);

    __half* vin_ptr = nullptr;
    __half* wH_ptr = nullptr;
    cudaGetSymbolAddress((void**)&vin_ptr, g_vin);
    cudaGetSymbolAddress((void**)&wH_ptr,  g_wH);

    wpre_kernel<<<72, 256>>>(cw);
    vin_prep<<<dim3(128, 8), 256>>>(r, d);
    zero_kernel<<<328, 256>>>();
    conv_mma<<<dim3(64, 2, 8), 256, CONV_SMEM>>>(vin_ptr, wH_ptr);
    hist_kernel<<<8, 256>>>(lab);
    stats_mma<<<dim3(16, 8, 2), 256>>>(d, lab);
    gate_kernel<<<dim3(8, 2), 128>>>(fw1, fw2, dw1, dw2, bf, bd);
    out_kernel<<<16384, 256>>>(d, out);
}